// round 12
// baseline (speedup 1.0000x reference)
#include <cuda_runtime.h>
#include <cstddef>

#define N_ROWS 8192
#define N_COLS 8192
#define TPB 512
#define NB 2048            // bins per region (pos / neg)
#define NBT (2 * NB)       // 4096 total bins
#define N_STEPS 100
#define EPSF 1.1920928955078125e-07f

struct Smem {
    double s1p[NBT + 1];            // exclusive fp64 prefix of per-bin sum(V)
    double lossParts[2][N_STEPS];
    double taskA[TPB];
    double wscanD[16];
    double s2red[16][2];
    double s2tot[2];
    int    taskB[TPB];
    int    cntP[NBT + 1];           // exclusive prefix of counts
    int    off[NBT];                // histogram, then scatter cursors
    int    wscanI[16];
    float  losses[N_STEPS];
    float  redmin[16], redmax[16];
    float  Rsh, rminS, rmaxS;
    float  sv[N_COLS];              // V = |x| grouped by bin
};

__global__ void __launch_bounds__(TPB)
obs_kernel(const float* __restrict__ x, float* __restrict__ out) {
    extern __shared__ char smraw[];
    Smem& S = *reinterpret_cast<Smem*>(smraw);
    const int row  = blockIdx.x;
    const int tid  = threadIdx.x;
    const int lane = tid & 31;
    const int wid  = tid >> 5;
    const float* xr = x + (size_t)row * N_COLS;

    // ---- Phase 1: load 16 elements/thread, row min/max ----
    float raw[16];
    {
        const float4* x4 = (const float4*)xr;
        #pragma unroll
        for (int k = 0; k < 4; k++) {
            float4 f = x4[tid + k * TPB];
            raw[k * 4 + 0] = f.x; raw[k * 4 + 1] = f.y;
            raw[k * 4 + 2] = f.z; raw[k * 4 + 3] = f.w;
        }
    }
    float mn = raw[0], mx = raw[0];
    #pragma unroll
    for (int m = 1; m < 16; m++) { mn = fminf(mn, raw[m]); mx = fmaxf(mx, raw[m]); }
    #pragma unroll
    for (int o = 16; o; o >>= 1) {
        mn = fminf(mn, __shfl_xor_sync(~0u, mn, o));
        mx = fmaxf(mx, __shfl_xor_sync(~0u, mx, o));
    }
    if (lane == 0) { S.redmin[wid] = mn; S.redmax[wid] = mx; }
    for (int j = tid; j < NBT; j += TPB) S.off[j] = 0;   // zero histogram
    __syncthreads();
    if (tid == 0) {
        float a = S.redmin[0], b = S.redmax[0];
        for (int w = 1; w < 16; w++) { a = fminf(a, S.redmin[w]); b = fmaxf(b, S.redmax[w]); }
        S.rminS = a; S.rmaxS = b;
        S.Rsh = fmaxf(fabsf(a), b);
    }
    __syncthreads();
    const float R = S.Rsh;
    const float binScale = __fdiv_rn((float)NB, R);

    // ---- Phase 2: bin + histogram + per-region sum(V^2) in fp64 ----
    int gbin[16];
    double s2p = 0.0, s2n = 0.0;
    #pragma unroll
    for (int m = 0; m < 16; m++) {
        float v = fabsf(raw[m]);
        int neg = (int)(__float_as_uint(raw[m]) >> 31);
        int b = (int)(v * binScale);
        b = min(b, NB - 1);
        gbin[m] = b + neg * NB;
        atomicAdd(&S.off[gbin[m]], 1);
        double vv = (double)v * (double)v;   // exact (24-bit^2 fits in 53)
        if (neg) s2n += vv; else s2p += vv;
    }
    #pragma unroll
    for (int o = 16; o; o >>= 1) {
        s2p += __shfl_xor_sync(~0u, s2p, o);
        s2n += __shfl_xor_sync(~0u, s2n, o);
    }
    if (lane == 0) { S.s2red[wid][0] = s2p; S.s2red[wid][1] = s2n; }
    __syncthreads();
    if (tid == 0) {
        double a = 0.0, b = 0.0;
        for (int w = 0; w < 16; w++) { a += S.s2red[w][0]; b += S.s2red[w][1]; }
        S.s2tot[0] = a; S.s2tot[1] = b;
    }

    // ---- Phase 3: exclusive int scan off -> cntP (8 bins/thread) ----
    {
        const int base = tid * 8;
        int loc[8], run = 0;
        #pragma unroll
        for (int m = 0; m < 8; m++) { loc[m] = run; run += S.off[base + m]; }
        int inc = run;
        #pragma unroll
        for (int o = 1; o < 32; o <<= 1) {
            int t = __shfl_up_sync(~0u, inc, o);
            if (lane >= o) inc += t;
        }
        int excl = __shfl_up_sync(~0u, inc, 1);
        if (lane == 0) excl = 0;
        if (lane == 31) S.wscanI[wid] = inc;
        __syncthreads();
        if (tid == 0) {
            int a = 0;
            for (int w = 0; w < 16; w++) { int t = S.wscanI[w]; S.wscanI[w] = a; a += t; }
        }
        __syncthreads();
        int texcl = excl + S.wscanI[wid];
        #pragma unroll
        for (int m = 0; m < 8; m++) S.cntP[base + m] = texcl + loc[m];
        if (tid == TPB - 1) S.cntP[NBT] = texcl + run;
    }
    __syncthreads();
    for (int j = tid; j < NBT; j += TPB) S.off[j] = S.cntP[j];   // scatter cursors
    __syncthreads();

    // ---- Phase 4: scatter V by bin ----
    #pragma unroll
    for (int m = 0; m < 16; m++) {
        int p = atomicAdd(&S.off[gbin[m]], 1);
        S.sv[p] = fabsf(raw[m]);
    }
    __syncthreads();

    // ---- Phase 5: per-bin sum(V) in fp64, exclusive scan -> s1p ----
    {
        const int base = tid * 8;
        double loc[8], run = 0.0;
        #pragma unroll
        for (int m = 0; m < 8; m++) {
            loc[m] = run;
            double ssum = 0.0;
            int k0 = S.cntP[base + m], k1 = S.cntP[base + m + 1];
            for (int k = k0; k < k1; k++) ssum += (double)S.sv[k];
            run += ssum;
        }
        double inc = run;
        #pragma unroll
        for (int o = 1; o < 32; o <<= 1) {
            double t = __shfl_up_sync(~0u, inc, o);
            if (lane >= o) inc += t;
        }
        double excl = __shfl_up_sync(~0u, inc, 1);
        if (lane == 0) excl = 0.0;
        if (lane == 31) S.wscanD[wid] = inc;
        __syncthreads();
        if (tid == 0) {
            double a = 0.0;
            for (int w = 0; w < 16; w++) { double t = S.wscanD[w]; S.wscanD[w] = a; a += t; }
        }
        __syncthreads();
        double texcl = excl + S.wscanD[wid];
        #pragma unroll
        for (int m = 0; m < 8; m++) S.s1p[base + m] = texcl + loc[m];
        if (tid == TPB - 1) S.s1p[NBT] = texcl + run;
    }
    __syncthreads();

    // ---- Phase 6: per-(step,region) boundary accumulation.
    // loss_reg = S2 - 2s*cb*S1 + s^2*cb^2*n + 2s*A - s^2*B,
    //   A = sum_q S1(b_q) (fp64), B = sum_q (2q-1)*n(b_q) (exact int),
    //   b_q = (q-0.5)*s, prefix = strict V < b.
    // 400 threads: 2 per task (even/odd q).
    if (tid < 400) {
        const int task = tid >> 1, sub = tid & 1;
        const int i = (task % 100) + 1;
        const int r = task / 100;                 // 0 = pos, 1 = neg
        const int cb = r ? 128 : 127;
        float rdiv  = __fdiv_rn(R, 100.0f);
        float thres = rdiv * (float)i;
        float s = fmaxf(__fdiv_rn(thres, 127.5f), EPSF);
        const int regBase = r * NB;
        const int    n0  = S.cntP[regBase];
        const double S10 = S.s1p[regBase];
        const int    nReg  = S.cntP[regBase + NB] - n0;
        const double S1reg = S.s1p[regBase + NB] - S10;
        double A = 0.0;
        int    B = 0;
        for (int q = 1 + sub; q <= cb; q += 2) {
            float b = ((float)q - 0.5f) * s;
            int j = (int)(b * binScale);
            double S1b; int nb;
            if (j >= NB) {
                nb = nReg; S1b = S1reg;
            } else {
                int g  = regBase + j;
                int k0 = S.cntP[g], k1 = S.cntP[g + 1];
                nb  = k0 - n0;
                S1b = S.s1p[g] - S10;
                for (int k = k0; k < k1; k++) {
                    float vv = S.sv[k];
                    if (vv < b) { S1b += (double)vv; nb++; }
                }
            }
            A += S1b;
            B += (2 * q - 1) * nb;
        }
        S.taskA[tid] = A;
        S.taskB[tid] = B;
    }
    __syncthreads();
    if (tid < 200) {
        const int i = (tid % 100) + 1;
        const int r = tid / 100;
        const int cb = r ? 128 : 127;
        float rdiv  = __fdiv_rn(R, 100.0f);
        float thres = rdiv * (float)i;
        float s = fmaxf(__fdiv_rn(thres, 127.5f), EPSF);
        double sd  = (double)s;
        double A = S.taskA[2 * tid] + S.taskA[2 * tid + 1];
        double B = (double)(S.taskB[2 * tid] + S.taskB[2 * tid + 1]);
        const int regBase = r * NB;
        double S1reg = S.s1p[regBase + NB] - S.s1p[regBase];
        double nReg  = (double)(S.cntP[regBase + NB] - S.cntP[regBase]);
        double cbd = (double)cb;
        double part = S.s2tot[r]
                    - 2.0 * sd * cbd * S1reg
                    + sd * sd * cbd * cbd * nReg
                    + 2.0 * sd * A
                    - sd * sd * B;
        S.lossParts[r][i - 1] = part;
    }
    __syncthreads();
    if (tid < N_STEPS)
        S.losses[tid] = (float)((S.lossParts[0][tid] + S.lossParts[1][tid]) * (1.0 / 8192.0));
    __syncthreads();

    // ---- Phase 7: sequential argmin (lax.scan semantics, strict <) ----
    if (tid == 0) {
        float best = 1.0e9f;
        float bmin = S.rminS, bmax = S.rmaxS;
        float rdiv = __fdiv_rn(R, 100.0f);
        for (int j = 0; j < N_STEPS; j++) {
            float L = S.losses[j];
            float th = rdiv * (float)(j + 1);
            if (L < best) { best = L; bmin = -th; bmax = th; }
        }
        out[row] = bmin;
        out[N_ROWS + row] = bmax;
    }
}

extern "C" void kernel_launch(void* const* d_in, const int* in_sizes, int n_in,
                              void* d_out, int out_size) {
    const float* x = (const float*)d_in[0];
    float* out = (float*)d_out;
    cudaFuncSetAttribute(obs_kernel, cudaFuncAttributeMaxDynamicSharedMemorySize,
                         (int)sizeof(Smem));
    obs_kernel<<<N_ROWS, TPB, sizeof(Smem)>>>(x, out);
}

// round 13
// speedup vs baseline: 6.0128x; 6.0128x over previous
#include <cuda_runtime.h>
#include <cstddef>

#define N_ROWS 8192
#define N_COLS 8192
#define TPB 512
#define NB 1024            // bins per region (pos / neg)
#define NBT (2 * NB)       // 2048 total bins
#define N_STEPS 100
#define N_TASKS (N_STEPS * 2 * 8)   // step x region x 16-q strips = 1600
#define EPSF 1.1920928955078125e-07f

struct Smem {
    long long s1p[NBT + 1];          // exclusive prefix of per-bin sum(I), int64
    long long Aacc[2 * N_STEPS];     // per (region,step) A accumulator
    long long wscanL[16];
    double lossParts[2][N_STEPS];
    double s2red[16][2];
    double s2tot[2];
    int   Bacc[2 * N_STEPS];
    int   cntP[NBT + 1];             // exclusive prefix of counts
    int   off[NBT];                  // histogram, then scatter cursors
    int   wscanI[16];
    int   svI[N_COLS];               // I = V*2^24/R grouped by bin
    float losses[N_STEPS];
    float redmin[16], redmax[16];
    float Rsh, rminS, rmaxS;
};

__global__ void __launch_bounds__(TPB)
obs_kernel(const float* __restrict__ x, float* __restrict__ out) {
    extern __shared__ char smraw[];
    Smem& S = *reinterpret_cast<Smem*>(smraw);
    const int row  = blockIdx.x;
    const int tid  = threadIdx.x;
    const int lane = tid & 31;
    const int wid  = tid >> 5;
    const float* xr = x + (size_t)row * N_COLS;

    // ---- Phase 1: load 16 elements/thread, row min/max; zero tables ----
    float raw[16];
    {
        const float4* x4 = (const float4*)xr;
        #pragma unroll
        for (int k = 0; k < 4; k++) {
            float4 f = x4[tid + k * TPB];
            raw[k * 4 + 0] = f.x; raw[k * 4 + 1] = f.y;
            raw[k * 4 + 2] = f.z; raw[k * 4 + 3] = f.w;
        }
    }
    float mn = raw[0], mx = raw[0];
    #pragma unroll
    for (int m = 1; m < 16; m++) { mn = fminf(mn, raw[m]); mx = fmaxf(mx, raw[m]); }
    #pragma unroll
    for (int o = 16; o; o >>= 1) {
        mn = fminf(mn, __shfl_xor_sync(~0u, mn, o));
        mx = fmaxf(mx, __shfl_xor_sync(~0u, mx, o));
    }
    if (lane == 0) { S.redmin[wid] = mn; S.redmax[wid] = mx; }
    #pragma unroll
    for (int j = tid; j < NBT; j += TPB) S.off[j] = 0;
    if (tid < 2 * N_STEPS) { S.Aacc[tid] = 0; S.Bacc[tid] = 0; }
    __syncthreads();
    if (tid == 0) {
        float a = S.redmin[0], b = S.redmax[0];
        for (int w = 1; w < 16; w++) { a = fminf(a, S.redmin[w]); b = fmaxf(b, S.redmax[w]); }
        S.rminS = a; S.rmaxS = b;
        S.Rsh = fmaxf(fabsf(a), b);
    }
    __syncthreads();
    const float R = S.Rsh;
    const float binScale = __fdiv_rn((float)NB, R);
    const float iScale   = __fdiv_rn(16777216.0f, R);   // V -> 24-bit int units

    // ---- Phase 2: histogram + per-region sum(V^2) in fp64 (independent adds) ----
    double s2p = 0.0, s2n = 0.0;
    #pragma unroll
    for (int m = 0; m < 16; m++) {
        float v = fabsf(raw[m]);
        int neg = (int)(__float_as_uint(raw[m]) >> 31);
        int b = min((int)(v * binScale), NB - 1) + neg * NB;
        atomicAdd(&S.off[b], 1);
        double vv = (double)v * (double)v;
        if (neg) s2n += vv; else s2p += vv;
    }
    #pragma unroll
    for (int o = 16; o; o >>= 1) {
        s2p += __shfl_xor_sync(~0u, s2p, o);
        s2n += __shfl_xor_sync(~0u, s2n, o);
    }
    if (lane == 0) { S.s2red[wid][0] = s2p; S.s2red[wid][1] = s2n; }
    __syncthreads();
    if (tid == 0) {
        double a = 0.0, b = 0.0;
        for (int w = 0; w < 16; w++) { a += S.s2red[w][0]; b += S.s2red[w][1]; }
        S.s2tot[0] = a; S.s2tot[1] = b;
    }

    // ---- Phase 3: exclusive int scan off -> cntP (4 bins/thread) ----
    {
        const int base = tid * 4;
        int loc[4], run = 0;
        #pragma unroll
        for (int m = 0; m < 4; m++) { loc[m] = run; run += S.off[base + m]; }
        int inc = run;
        #pragma unroll
        for (int o = 1; o < 32; o <<= 1) {
            int t = __shfl_up_sync(~0u, inc, o);
            if (lane >= o) inc += t;
        }
        int excl = __shfl_up_sync(~0u, inc, 1);
        if (lane == 0) excl = 0;
        if (lane == 31) S.wscanI[wid] = inc;
        __syncthreads();
        if (tid == 0) {
            int a = 0;
            for (int w = 0; w < 16; w++) { int t = S.wscanI[w]; S.wscanI[w] = a; a += t; }
        }
        __syncthreads();
        int texcl = excl + S.wscanI[wid];
        #pragma unroll
        for (int m = 0; m < 4; m++) S.cntP[base + m] = texcl + loc[m];
        if (tid == TPB - 1) S.cntP[NBT] = texcl + run;
    }
    __syncthreads();
    for (int j = tid; j < NBT; j += TPB) S.off[j] = S.cntP[j];
    __syncthreads();

    // ---- Phase 4: scatter I by bin (recompute bin/I from raw; low regs) ----
    #pragma unroll
    for (int m = 0; m < 16; m++) {
        float v = fabsf(raw[m]);
        int neg = (int)(__float_as_uint(raw[m]) >> 31);
        int b = min((int)(v * binScale), NB - 1) + neg * NB;
        int p = atomicAdd(&S.off[b], 1);
        S.svI[p] = (int)(v * iScale);
    }
    __syncthreads();

    // ---- Phase 5: per-bin int64 sums + exclusive scan -> s1p (IADD chains) ----
    {
        const int base = tid * 4;
        long long loc[4], run = 0;
        #pragma unroll
        for (int m = 0; m < 4; m++) {
            loc[m] = run;
            long long ssum = 0;
            int k0 = S.cntP[base + m], k1 = S.cntP[base + m + 1];
            for (int k = k0; k < k1; k++) ssum += (long long)S.svI[k];
            run += ssum;
        }
        long long inc = run;
        #pragma unroll
        for (int o = 1; o < 32; o <<= 1) {
            long long t = __shfl_up_sync(~0u, inc, o);
            if (lane >= o) inc += t;
        }
        long long excl = __shfl_up_sync(~0u, inc, 1);
        if (lane == 0) excl = 0;
        if (lane == 31) S.wscanL[wid] = inc;
        __syncthreads();
        if (tid == 0) {
            long long a = 0;
            for (int w = 0; w < 16; w++) { long long t = S.wscanL[w]; S.wscanL[w] = a; a += t; }
        }
        __syncthreads();
        long long texcl = excl + S.wscanL[wid];
        #pragma unroll
        for (int m = 0; m < 4; m++) S.s1p[base + m] = texcl + loc[m];
        if (tid == TPB - 1) S.s1p[NBT] = texcl + run;
    }
    __syncthreads();

    // ---- Phase 6: flat boundary tasks. task = (strip, region, step).
    // loss_reg = S2 - 2s*cb*S1 + s^2*cb^2*n + 2s*A - s^2*B  (validated in R11),
    // A = sum_q S1(b_q) [int64 I-units], B = sum_q (2q-1)*n(b_q) [int].
    {
        const float rdiv = __fdiv_rn(R, 100.0f);
        for (int t = tid; t < N_TASKS; t += TPB) {
            const int strip = t & 7;
            const int r     = (t >> 3) & 1;
            const int step  = t >> 4;
            const int cb = r ? 128 : 127;
            float thres = rdiv * (float)(step + 1);
            float s = fmaxf(__fdiv_rn(thres, 127.5f), EPSF);
            const int q0  = strip * 16 + 1;
            const int qhi = min(q0 + 15, cb);
            const int regBase = r * NB;
            const int       n0  = S.cntP[regBase];
            const long long S10 = S.s1p[regBase];
            long long A = 0;
            int       B = 0;
            for (int q = q0; q <= qhi; q++) {
                float b = ((float)q - 0.5f) * s;
                int j = (int)(b * binScale);
                long long S1b; int nb;
                if (j >= NB) {
                    nb  = S.cntP[regBase + NB] - n0;
                    S1b = S.s1p[regBase + NB] - S10;
                } else {
                    int g  = regBase + j;
                    int k0 = S.cntP[g], k1 = S.cntP[g + 1];
                    nb  = k0 - n0;
                    S1b = S.s1p[g] - S10;
                    int Bq = (int)(b * iScale);
                    for (int k = k0; k < k1; k++) {
                        int Iv = S.svI[k];
                        if (Iv < Bq) { S1b += (long long)Iv; nb++; }
                    }
                }
                A += S1b;
                B += (2 * q - 1) * nb;
            }
            atomicAdd((unsigned long long*)&S.Aacc[r * N_STEPS + step],
                      (unsigned long long)A);
            atomicAdd(&S.Bacc[r * N_STEPS + step], B);
        }
    }
    __syncthreads();

    // ---- Phase 6b: combine per (region,step) in fp64 (200 threads, cheap) ----
    if (tid < 200) {
        const int r    = tid / 100;
        const int step = tid % 100;
        const int cb = r ? 128 : 127;
        float rdiv  = __fdiv_rn(R, 100.0f);
        float thres = rdiv * (float)(step + 1);
        float s = fmaxf(__fdiv_rn(thres, 127.5f), EPSF);
        double sd   = (double)s;
        double iInv = 1.0 / (double)iScale;       // I-units -> V-units
        const int regBase = r * NB;
        double S1reg = (double)(S.s1p[regBase + NB] - S.s1p[regBase]) * iInv;
        double nReg  = (double)(S.cntP[regBase + NB] - S.cntP[regBase]);
        double A     = (double)S.Aacc[r * N_STEPS + step] * iInv;
        double B     = (double)S.Bacc[r * N_STEPS + step];
        double cbd   = (double)cb;
        S.lossParts[r][step] = S.s2tot[r]
                             - 2.0 * sd * cbd * S1reg
                             + sd * sd * cbd * cbd * nReg
                             + 2.0 * sd * A
                             - sd * sd * B;
    }
    __syncthreads();
    if (tid < N_STEPS)
        S.losses[tid] = (float)((S.lossParts[0][tid] + S.lossParts[1][tid]) * (1.0 / 8192.0));
    __syncthreads();

    // ---- Phase 7: sequential argmin (lax.scan semantics, strict <) ----
    if (tid == 0) {
        float best = 1.0e9f;
        float bmin = S.rminS, bmax = S.rmaxS;
        float rdiv = __fdiv_rn(R, 100.0f);
        for (int j = 0; j < N_STEPS; j++) {
            float L = S.losses[j];
            float th = rdiv * (float)(j + 1);
            if (L < best) { best = L; bmin = -th; bmax = th; }
        }
        out[row] = bmin;
        out[N_ROWS + row] = bmax;
    }
}

extern "C" void kernel_launch(void* const* d_in, const int* in_sizes, int n_in,
                              void* d_out, int out_size) {
    const float* x = (const float*)d_in[0];
    float* out = (float*)d_out;
    cudaFuncSetAttribute(obs_kernel, cudaFuncAttributeMaxDynamicSharedMemorySize,
                         (int)sizeof(Smem));
    obs_kernel<<<N_ROWS, TPB, sizeof(Smem)>>>(x, out);
}

// round 14
// speedup vs baseline: 10.4122x; 1.7317x over previous
#include <cuda_runtime.h>
#include <cstddef>

#define N_ROWS 8192
#define N_COLS 8192
#define THREADS 256
#define N_STEPS 100
#define HALF_STEPS 50
#define NITER (N_COLS / 128)   // 64 iterations x 2 elements per 64-thread group
#define MAXC 14                // max local steps per group

// Cross-kernel scratch (device globals: allowed; no allocation).
__device__ float g_loss[N_STEPS][N_ROWS];   // losses[step][row]
__device__ float g_aux[2][N_ROWS];          // [0]=rmin, [1]=rmax per row

__device__ __forceinline__ float shfl_add(float v) {
    #pragma unroll
    for (int o = 16; o; o >>= 1) v += __shfl_xor_sync(0xFFFFFFFFu, v, o);
    return v;
}

// R4-identical math, 2 elements per iteration (shared ivp, doubled ILP).
// u = |x|*inv;  rr = fma(|x|,inv,M) = M + round(u)  (exact; huge u clamped)
// rr = min(rr, M+cb), cb = 127 (x>=0) / 128 (x<0)
// nq = M - rr = -q (exact);  dd = fma(|x|,inv,nq) = u - q;  acc += dd*dd
template<int NP>
__device__ __forceinline__ void run_group(
    const float* __restrict__ row_sm, const float* __restrict__ invs,
    float (*partial)[MAXC], int base, int l64, int warp, int lane,
    unsigned long long M2)
{
    unsigned long long ivp[NP], app[NP];
    #pragma unroll
    for (int j = 0; j < NP; j++) {
        float a = invs[base + 2 * j], b = invs[base + 2 * j + 1];
        asm("mov.b64 %0, {%1,%2};" : "=l"(ivp[j]) : "f"(a), "f"(b));
        app[j] = 0ULL;
    }

    // software-pipelined loads: prefetch iteration k+1 while computing k
    float x0 = row_sm[l64];
    float x1 = row_sm[l64 + 64];
    for (int k = 0; k < NITER; k++) {
        float nx0 = 0.0f, nx1 = 0.0f;
        if (k + 1 < NITER) {
            nx0 = row_sm[l64 + (k + 1) * 128];
            nx1 = row_sm[l64 + 64 + (k + 1) * 128];
        }
        unsigned xb0 = __float_as_uint(x0);
        unsigned xb1 = __float_as_uint(x1);
        float ax0 = __uint_as_float(xb0 & 0x7FFFFFFFu);
        float ax1 = __uint_as_float(xb1 & 0x7FFFFFFFu);
        float cb0 = __uint_as_float(0x4B40007Fu + (xb0 >> 31));   // M+127/M+128
        float cb1 = __uint_as_float(0x4B40007Fu + (xb1 >> 31));
        unsigned long long aa0, aa1;
        asm("mov.b64 %0, {%1,%1};" : "=l"(aa0) : "f"(ax0));
        asm("mov.b64 %0, {%1,%1};" : "=l"(aa1) : "f"(ax1));
        #pragma unroll
        for (int j = 0; j < NP; j++) {
            asm("{\n\t"
                ".reg .f32 p0,p1,q0,q1;\n\t"
                ".reg .b64 r0,r1,n0,n1,d0,d1;\n\t"
                "fma.rn.f32x2 r0, %1, %3, %4;\n\t"   // M + round(u0)  [fma rt3]
                "fma.rn.f32x2 r1, %2, %3, %4;\n\t"   // M + round(u1)  [fma rt3]
                "mov.b64 {p0,p1}, r0;\n\t"
                "mov.b64 {q0,q1}, r1;\n\t"
                "min.f32 p0, p0, %5;\n\t"            // clamp          [alu]
                "min.f32 p1, p1, %5;\n\t"
                "min.f32 q0, q0, %6;\n\t"
                "min.f32 q1, q1, %6;\n\t"
                "mov.b64 r0, {p0,p1};\n\t"
                "mov.b64 r1, {q0,q1};\n\t"
                "sub.rn.f32x2 n0, %4, r0;\n\t"       // -q exact       [fma rt2]
                "sub.rn.f32x2 n1, %4, r1;\n\t"
                "fma.rn.f32x2 d0, %1, %3, n0;\n\t"   // u0 - q0        [fma rt3]
                "fma.rn.f32x2 d1, %2, %3, n1;\n\t"   // u1 - q1        [fma rt3]
                "fma.rn.f32x2 %0, d0, d0, %0;\n\t"   // acc += d0*d0   [fma rt2]
                "fma.rn.f32x2 %0, d1, d1, %0;\n\t"   // acc += d1*d1   [fma rt2]
                "}"
                : "+l"(app[j])
                : "l"(aa0), "l"(aa1), "l"(ivp[j]), "l"(M2), "f"(cb0), "f"(cb1));
        }
        x0 = nx0; x1 = nx1;
    }

    #pragma unroll
    for (int j = 0; j < NP; j++) {
        float a0, a1;
        asm("mov.b64 {%0,%1}, %2;" : "=f"(a0), "=f"(a1) : "l"(app[j]));
        a0 = shfl_add(a0);
        a1 = shfl_add(a1);
        if (lane == 0) { partial[warp][2 * j] = a0; partial[warp][2 * j + 1] = a1; }
    }
}

// Kernel 1: grid (N_ROWS, 2). blockIdx.y selects which 50 steps this block owns.
__global__ __launch_bounds__(THREADS)
void mse_losses_kernel(const float* __restrict__ x, unsigned long long M2) {
    __shared__ float row_sm[N_COLS];
    __shared__ float invs[HALF_STEPS];     // 1/scale for this half's steps
    __shared__ float s2k[HALF_STEPS];      // scale^2 / 8192
    __shared__ float partial[8][MAXC];     // per-warp partials (group-local idx)
    __shared__ float red_min[8], red_max[8];
    __shared__ float Rsh;

    const int row  = blockIdx.x;
    const int half = blockIdx.y;
    const int tid  = threadIdx.x;
    const int warp = tid >> 5;
    const int lane = tid & 31;
    const float* xr = x + (size_t)row * N_COLS;

    // ---- Phase A: load row to smem, compute row min/max ----
    float mn = 3.0e38f, mx = -3.0e38f;
    const float4* xr4 = (const float4*)xr;
    float4* row4 = (float4*)row_sm;
    #pragma unroll
    for (int k = 0; k < N_COLS / 4 / THREADS; k++) {   // 8 iterations
        float4 v = xr4[tid + k * THREADS];
        row4[tid + k * THREADS] = v;
        mn = fminf(mn, fminf(fminf(v.x, v.y), fminf(v.z, v.w)));
        mx = fmaxf(mx, fmaxf(fmaxf(v.x, v.y), fmaxf(v.z, v.w)));
    }
    #pragma unroll
    for (int o = 16; o; o >>= 1) {
        mn = fminf(mn, __shfl_xor_sync(0xFFFFFFFFu, mn, o));
        mx = fmaxf(mx, __shfl_xor_sync(0xFFFFFFFFu, mx, o));
    }
    if (lane == 0) { red_min[warp] = mn; red_max[warp] = mx; }
    __syncthreads();
    if (tid == 0) {
        float m = red_min[0], M = red_max[0];
        #pragma unroll
        for (int w = 1; w < 8; w++) { m = fminf(m, red_min[w]); M = fmaxf(M, red_max[w]); }
        Rsh = fmaxf(fabsf(m), M);   // range_val = max(|min|, max)
        if (half == 0) {
            g_aux[0][row] = m;
            g_aux[1][row] = M;
        }
    }
    __syncthreads();

    // ---- Phase B: per-step tables for this half's 50 steps ----
    if (tid < HALF_STEPS) {
        float R = Rsh;
        int   sg = half * HALF_STEPS + tid;          // global step index 0..99
        float thres = __fdiv_rn(R, 100.0f) * (float)(sg + 1);
        float scale = fmaxf(__fdiv_rn(thres, 127.5f), 1.1920928955078125e-07f);
        invs[tid] = __fdiv_rn(1.0f, scale);
        s2k[tid]  = scale * scale * (1.0f / 8192.0f);
    }
    __syncthreads();

    // ---- Phase C: 4 groups x {6,6,6,7} pairs = 25 pairs = 50 steps ----
    const int grp = tid >> 6;
    const int l64 = tid & 63;
    if (grp == 0)      run_group<6>(row_sm, invs, partial,  0, l64, warp, lane, M2);
    else if (grp == 1) run_group<6>(row_sm, invs, partial, 12, l64, warp, lane, M2);
    else if (grp == 2) run_group<6>(row_sm, invs, partial, 24, l64, warp, lane, M2);
    else               run_group<7>(row_sm, invs, partial, 36, l64, warp, lane, M2);
    __syncthreads();

    // ---- Phase D: combine warp pairs, write losses to scratch ----
    if (tid < HALF_STEPS) {
        int s = tid;                       // local step 0..49
        int g  = (s < 36) ? (s / 12) : 3;
        int jj = (s < 36) ? (s % 12) : (s - 36);
        float sum = partial[2 * g][jj] + partial[2 * g + 1][jj];
        g_loss[half * HALF_STEPS + s][row] = sum * s2k[s];
    }
}

// Kernel 2: per-row sequential argmin scan (matches lax.scan semantics).
__global__ __launch_bounds__(256)
void mse_argmin_kernel(float* __restrict__ out) {
    int row = blockIdx.x * 256 + threadIdx.x;
    if (row >= N_ROWS) return;
    float rmin = g_aux[0][row];
    float rmax = g_aux[1][row];
    float R = fmaxf(fabsf(rmin), rmax);
    float step_sz = __fdiv_rn(R, 100.0f);      // identical expr to kernel1
    float best = 1.0e9f;
    float bmin = rmin, bmax = rmax;
    for (int j = 0; j < N_STEPS; j++) {
        float L = g_loss[j][row];               // coalesced, L2-hot
        float thres = step_sz * (float)(j + 1);
        if (L < best) { best = L; bmin = -thres; bmax = thres; }
    }
    out[row] = bmin;
    out[N_ROWS + row] = bmax;
}

extern "C" void kernel_launch(void* const* d_in, const int* in_sizes, int n_in,
                              void* d_out, int out_size) {
    const float* x = (const float*)d_in[0];
    float* out = (float*)d_out;
    dim3 grid1(N_ROWS, 2);
    mse_losses_kernel<<<grid1, THREADS>>>(x, 0x4B4000004B400000ULL);
    mse_argmin_kernel<<<N_ROWS / 256, 256>>>(out);
}

// round 15
// speedup vs baseline: 12.1540x; 1.1673x over previous
#include <cuda_runtime.h>
#include <cstddef>

#define N_ROWS 8192
#define N_COLS 8192
#define THREADS 256
#define N_STEPS 100
#define HALF_STEPS 50
#define EPT (N_COLS / 64)   // elements per thread within a 64-thread group = 128
#define MAXC 14             // max local steps per group (group 3 has 14)

// Cross-kernel scratch (device globals: allowed; no allocation).
__device__ float g_loss[N_STEPS][N_ROWS];   // losses[step][row]
__device__ float g_aux[2][N_ROWS];          // [0]=rmin, [1]=rmax per row

__device__ __forceinline__ float shfl_add(float v) {
    #pragma unroll
    for (int o = 16; o; o >>= 1) v += __shfl_xor_sync(0xFFFFFFFFu, v, o);
    return v;
}

// R9-identical math; inner loop processes TWO j-pairs per asm block with
// pairwise interleaving so no instruction depends on its immediate
// predecessor (halves per-warp dependency stalls).
// u = |x|*inv;  rr = fma(|x|,inv,M) = M + round(u)  (exact; huge u clamped)
// rr = min(rr, M+cb), cb = 127 (x>=0) / 128 (x<0)
// nq = M - rr = -q (exact);  dd = fma(|x|,inv,nq) = u - q;  acc += dd*dd
template<int NP>
__device__ __forceinline__ void run_group(
    const float* __restrict__ row_sm, const float* __restrict__ invs,
    float (*partial)[MAXC], int base, int l64, int warp, int lane,
    unsigned long long M2)
{
    unsigned long long ivp[NP], app[NP];
    #pragma unroll
    for (int j = 0; j < NP; j++) {
        float a = invs[base + 2 * j], b = invs[base + 2 * j + 1];
        asm("mov.b64 %0, {%1,%2};" : "=l"(ivp[j]) : "f"(a), "f"(b));
        app[j] = 0ULL;
    }

    #pragma unroll 2
    for (int k = 0; k < EPT; k++) {
        float xv = row_sm[l64 + (k << 6)];
        unsigned xb = __float_as_uint(xv);
        float ax = __uint_as_float(xb & 0x7FFFFFFFu);            // |x|
        float cb = __uint_as_float(0x4B40007Fu + (xb >> 31));    // M+127 / M+128
        unsigned long long aa;
        asm("mov.b64 %0, {%1,%1};" : "=l"(aa) : "f"(ax));
        #pragma unroll
        for (int j = 0; j + 1 < NP; j += 2) {
            asm("{\n\t"
                ".reg .f32 a0,a1,b0,b1;\n\t"
                ".reg .b64 r0,r1,n0,n1,d0,d1;\n\t"
                "fma.rn.f32x2 r0, %2, %3, %5;\n\t"   // M + round(u) j    [fma]
                "fma.rn.f32x2 r1, %2, %4, %5;\n\t"   // M + round(u) j+1  [fma]
                "mov.b64 {a0,a1}, r0;\n\t"
                "mov.b64 {b0,b1}, r1;\n\t"
                "min.f32 a0, a0, %6;\n\t"            // clamp             [alu]
                "min.f32 a1, a1, %6;\n\t"
                "min.f32 b0, b0, %6;\n\t"
                "min.f32 b1, b1, %6;\n\t"
                "mov.b64 r0, {a0,a1};\n\t"
                "mov.b64 r1, {b0,b1};\n\t"
                "sub.rn.f32x2 n0, %5, r0;\n\t"       // -q exact          [fma]
                "sub.rn.f32x2 n1, %5, r1;\n\t"
                "fma.rn.f32x2 d0, %2, %3, n0;\n\t"   // u - q             [fma]
                "fma.rn.f32x2 d1, %2, %4, n1;\n\t"
                "fma.rn.f32x2 %0, d0, d0, %0;\n\t"   // acc j             [fma]
                "fma.rn.f32x2 %1, d1, d1, %1;\n\t"   // acc j+1           [fma]
                "}"
                : "+l"(app[j]), "+l"(app[j + 1])
                : "l"(aa), "l"(ivp[j]), "l"(ivp[j + 1]), "l"(M2), "f"(cb));
        }
        if (NP & 1) {
            const int j = NP - 1;
            asm("{\n\t"
                ".reg .f32 n0,n1;\n\t"
                ".reg .b64 rr,nq,dd;\n\t"
                "fma.rn.f32x2 rr, %1, %2, %3;\n\t"
                "mov.b64 {n0,n1}, rr;\n\t"
                "min.f32 n0, n0, %4;\n\t"
                "min.f32 n1, n1, %4;\n\t"
                "mov.b64 rr, {n0,n1};\n\t"
                "sub.rn.f32x2 nq, %3, rr;\n\t"
                "fma.rn.f32x2 dd, %1, %2, nq;\n\t"
                "fma.rn.f32x2 %0, dd, dd, %0;\n\t"
                "}"
                : "+l"(app[j])
                : "l"(aa), "l"(ivp[j]), "l"(M2), "f"(cb));
        }
    }

    #pragma unroll
    for (int j = 0; j < NP; j++) {
        float a0, a1;
        asm("mov.b64 {%0,%1}, %2;" : "=f"(a0), "=f"(a1) : "l"(app[j]));
        a0 = shfl_add(a0);
        a1 = shfl_add(a1);
        if (lane == 0) { partial[warp][2 * j] = a0; partial[warp][2 * j + 1] = a1; }
    }
}

// Kernel 1: grid (N_ROWS, 2). blockIdx.y selects which 50 steps this block owns.
__global__ __launch_bounds__(THREADS)
void mse_losses_kernel(const float* __restrict__ x, unsigned long long M2) {
    __shared__ float row_sm[N_COLS];
    __shared__ float invs[HALF_STEPS];     // 1/scale for this half's steps
    __shared__ float s2k[HALF_STEPS];      // scale^2 / 8192
    __shared__ float partial[8][MAXC];     // per-warp partials (group-local idx)
    __shared__ float red_min[8], red_max[8];
    __shared__ float Rsh;

    const int row  = blockIdx.x;
    const int half = blockIdx.y;
    const int tid  = threadIdx.x;
    const int warp = tid >> 5;
    const int lane = tid & 31;
    const float* xr = x + (size_t)row * N_COLS;

    // ---- Phase A: load row to smem, compute row min/max ----
    float mn = 3.0e38f, mx = -3.0e38f;
    const float4* xr4 = (const float4*)xr;
    float4* row4 = (float4*)row_sm;
    #pragma unroll
    for (int k = 0; k < N_COLS / 4 / THREADS; k++) {   // 8 iterations
        float4 v = xr4[tid + k * THREADS];
        row4[tid + k * THREADS] = v;
        mn = fminf(mn, fminf(fminf(v.x, v.y), fminf(v.z, v.w)));
        mx = fmaxf(mx, fmaxf(fmaxf(v.x, v.y), fmaxf(v.z, v.w)));
    }
    #pragma unroll
    for (int o = 16; o; o >>= 1) {
        mn = fminf(mn, __shfl_xor_sync(0xFFFFFFFFu, mn, o));
        mx = fmaxf(mx, __shfl_xor_sync(0xFFFFFFFFu, mx, o));
    }
    if (lane == 0) { red_min[warp] = mn; red_max[warp] = mx; }
    __syncthreads();
    if (tid == 0) {
        float m = red_min[0], M = red_max[0];
        #pragma unroll
        for (int w = 1; w < 8; w++) { m = fminf(m, red_min[w]); M = fmaxf(M, red_max[w]); }
        Rsh = fmaxf(fabsf(m), M);   // range_val = max(|min|, max)
        if (half == 0) {
            g_aux[0][row] = m;
            g_aux[1][row] = M;
        }
    }
    __syncthreads();

    // ---- Phase B: per-step tables for this half's 50 steps ----
    if (tid < HALF_STEPS) {
        float R = Rsh;
        int   sg = half * HALF_STEPS + tid;          // global step index 0..99
        float thres = __fdiv_rn(R, 100.0f) * (float)(sg + 1);
        float scale = fmaxf(__fdiv_rn(thres, 127.5f), 1.1920928955078125e-07f);
        invs[tid] = __fdiv_rn(1.0f, scale);
        s2k[tid]  = scale * scale * (1.0f / 8192.0f);
    }
    __syncthreads();

    // ---- Phase C: 4 groups x {6,6,6,7} pairs = 25 pairs = 50 steps ----
    const int grp = tid >> 6;
    const int l64 = tid & 63;
    if (grp == 0)      run_group<6>(row_sm, invs, partial,  0, l64, warp, lane, M2);
    else if (grp == 1) run_group<6>(row_sm, invs, partial, 12, l64, warp, lane, M2);
    else if (grp == 2) run_group<6>(row_sm, invs, partial, 24, l64, warp, lane, M2);
    else               run_group<7>(row_sm, invs, partial, 36, l64, warp, lane, M2);
    __syncthreads();

    // ---- Phase D: combine warp pairs, write losses to scratch ----
    if (tid < HALF_STEPS) {
        int s = tid;                       // local step 0..49
        int g  = (s < 36) ? (s / 12) : 3;
        int jj = (s < 36) ? (s % 12) : (s - 36);
        float sum = partial[2 * g][jj] + partial[2 * g + 1][jj];
        g_loss[half * HALF_STEPS + s][row] = sum * s2k[s];
    }
}

// Kernel 2: per-row sequential argmin scan (matches lax.scan semantics).
__global__ __launch_bounds__(256)
void mse_argmin_kernel(float* __restrict__ out) {
    int row = blockIdx.x * 256 + threadIdx.x;
    if (row >= N_ROWS) return;
    float rmin = g_aux[0][row];
    float rmax = g_aux[1][row];
    float R = fmaxf(fabsf(rmin), rmax);
    float step_sz = __fdiv_rn(R, 100.0f);      // identical expr to kernel1
    float best = 1.0e9f;
    float bmin = rmin, bmax = rmax;
    for (int j = 0; j < N_STEPS; j++) {
        float L = g_loss[j][row];               // coalesced, L2-hot
        float thres = step_sz * (float)(j + 1);
        if (L < best) { best = L; bmin = -thres; bmax = thres; }
    }
    out[row] = bmin;
    out[N_ROWS + row] = bmax;
}

extern "C" void kernel_launch(void* const* d_in, const int* in_sizes, int n_in,
                              void* d_out, int out_size) {
    const float* x = (const float*)d_in[0];
    float* out = (float*)d_out;
    dim3 grid1(N_ROWS, 2);
    mse_losses_kernel<<<grid1, THREADS>>>(x, 0x4B4000004B400000ULL);
    mse_argmin_kernel<<<N_ROWS / 256, 256>>>(out);
}

// round 16
// speedup vs baseline: 12.8808x; 1.0598x over previous
#include <cuda_runtime.h>
#include <cstddef>

#define N_ROWS 8192
#define N_COLS 8192
#define THREADS 320          // 5 groups x 64 threads: 25 pairs -> 5 per group, balanced
#define NWARP (THREADS / 32) // 10
#define N_STEPS 100
#define HALF_STEPS 50
#define EPT (N_COLS / 64)    // elements per thread within a 64-thread group = 128
#define NP 5                 // pairs per group (uniform!)
#define MAXC (2 * NP)        // 10 local steps per group

// Cross-kernel scratch (device globals: allowed; no allocation).
__device__ float g_loss[N_STEPS][N_ROWS];   // losses[step][row]
__device__ float g_aux[2][N_ROWS];          // [0]=rmin, [1]=rmax per row

__device__ __forceinline__ float shfl_add(float v) {
    #pragma unroll
    for (int o = 16; o; o >>= 1) v += __shfl_xor_sync(0xFFFFFFFFu, v, o);
    return v;
}

// R9-identical math. 64-thread group evaluates NP packed step-pairs.
// u = |x|*inv;  rr = fma(|x|,inv,M) = M + round(u)  (exact; huge u clamped)
// rr = min(rr, M+cb), cb = 127 (x>=0) / 128 (x<0)
// nq = M - rr = -q (exact);  dd = fma(|x|,inv,nq) = u - q;  acc += dd*dd
__device__ __forceinline__ void run_group(
    const float* __restrict__ row_sm, const float* __restrict__ invs,
    float (*partial)[MAXC], int base, int l64, int warp, int lane,
    unsigned long long M2)
{
    unsigned long long ivp[NP], app[NP];
    #pragma unroll
    for (int j = 0; j < NP; j++) {
        float a = invs[base + 2 * j], b = invs[base + 2 * j + 1];
        asm("mov.b64 %0, {%1,%2};" : "=l"(ivp[j]) : "f"(a), "f"(b));
        app[j] = 0ULL;
    }

    #pragma unroll 2
    for (int k = 0; k < EPT; k++) {
        float xv = row_sm[l64 + (k << 6)];
        unsigned xb = __float_as_uint(xv);
        float ax = __uint_as_float(xb & 0x7FFFFFFFu);            // |x|
        float cb = __uint_as_float(0x4B40007Fu + (xb >> 31));    // M+127 / M+128
        unsigned long long aa;
        asm("mov.b64 %0, {%1,%1};" : "=l"(aa) : "f"(ax));
        #pragma unroll
        for (int j = 0; j < NP; j++) {
            asm("{\n\t"
                ".reg .f32 n0,n1;\n\t"
                ".reg .b64 rr,nq,dd;\n\t"
                "fma.rn.f32x2 rr, %1, %2, %3;\n\t"   // M + round(u)   [fma rt3]
                "mov.b64 {n0,n1}, rr;\n\t"
                "min.f32 n0, n0, %4;\n\t"            // clamp          [alu]
                "min.f32 n1, n1, %4;\n\t"
                "mov.b64 rr, {n0,n1};\n\t"
                "sub.rn.f32x2 nq, %3, rr;\n\t"       // -q exact       [fma rt2]
                "fma.rn.f32x2 dd, %1, %2, nq;\n\t"   // u - q          [fma rt3]
                "fma.rn.f32x2 %0, dd, dd, %0;\n\t"   // acc += d*d     [fma rt2]
                "}"
                : "+l"(app[j])
                : "l"(aa), "l"(ivp[j]), "l"(M2), "f"(cb));
        }
    }

    #pragma unroll
    for (int j = 0; j < NP; j++) {
        float a0, a1;
        asm("mov.b64 {%0,%1}, %2;" : "=f"(a0), "=f"(a1) : "l"(app[j]));
        a0 = shfl_add(a0);
        a1 = shfl_add(a1);
        if (lane == 0) { partial[warp][2 * j] = a0; partial[warp][2 * j + 1] = a1; }
    }
}

// Kernel 1: grid (N_ROWS, 2). blockIdx.y selects which 50 steps this block owns.
__global__ __launch_bounds__(THREADS)
void mse_losses_kernel(const float* __restrict__ x, unsigned long long M2) {
    __shared__ float row_sm[N_COLS];
    __shared__ float invs[HALF_STEPS];     // 1/scale for this half's steps
    __shared__ float s2k[HALF_STEPS];      // scale^2 / 8192
    __shared__ float partial[NWARP][MAXC]; // per-warp partials (group-local idx)
    __shared__ float red_min[NWARP], red_max[NWARP];
    __shared__ float Rsh;

    const int row  = blockIdx.x;
    const int half = blockIdx.y;
    const int tid  = threadIdx.x;
    const int warp = tid >> 5;
    const int lane = tid & 31;
    const float* xr = x + (size_t)row * N_COLS;

    // ---- Phase A: load row to smem, compute row min/max ----
    // 2048 float4s over 320 threads: 6 full strides + 128-thread tail.
    float mn = 3.0e38f, mx = -3.0e38f;
    const float4* xr4 = (const float4*)xr;
    float4* row4 = (float4*)row_sm;
    #pragma unroll
    for (int k = 0; k < 7; k++) {
        int idx = tid + k * THREADS;
        if (idx < N_COLS / 4) {
            float4 v = xr4[idx];
            row4[idx] = v;
            mn = fminf(mn, fminf(fminf(v.x, v.y), fminf(v.z, v.w)));
            mx = fmaxf(mx, fmaxf(fmaxf(v.x, v.y), fmaxf(v.z, v.w)));
        }
    }
    #pragma unroll
    for (int o = 16; o; o >>= 1) {
        mn = fminf(mn, __shfl_xor_sync(0xFFFFFFFFu, mn, o));
        mx = fmaxf(mx, __shfl_xor_sync(0xFFFFFFFFu, mx, o));
    }
    if (lane == 0) { red_min[warp] = mn; red_max[warp] = mx; }
    __syncthreads();
    if (tid == 0) {
        float m = red_min[0], M = red_max[0];
        #pragma unroll
        for (int w = 1; w < NWARP; w++) { m = fminf(m, red_min[w]); M = fmaxf(M, red_max[w]); }
        Rsh = fmaxf(fabsf(m), M);   // range_val = max(|min|, max)
        if (half == 0) {
            g_aux[0][row] = m;
            g_aux[1][row] = M;
        }
    }
    __syncthreads();

    // ---- Phase B: per-step tables for this half's 50 steps ----
    if (tid < HALF_STEPS) {
        float R = Rsh;
        int   sg = half * HALF_STEPS + tid;          // global step index 0..99
        float thres = __fdiv_rn(R, 100.0f) * (float)(sg + 1);
        float scale = fmaxf(__fdiv_rn(thres, 127.5f), 1.1920928955078125e-07f);
        invs[tid] = __fdiv_rn(1.0f, scale);
        s2k[tid]  = scale * scale * (1.0f / 8192.0f);
    }
    __syncthreads();

    // ---- Phase C: 5 groups x 5 pairs = 25 pairs = 50 steps (balanced) ----
    const int grp = tid >> 6;          // 0..4
    const int l64 = tid & 63;
    run_group(row_sm, invs, partial, grp * MAXC, l64, warp, lane, M2);
    __syncthreads();

    // ---- Phase D: combine warp pairs, write losses to scratch ----
    if (tid < HALF_STEPS) {
        int g  = tid / MAXC;           // group 0..4
        int jj = tid % MAXC;           // local step 0..9
        float sum = partial[2 * g][jj] + partial[2 * g + 1][jj];
        g_loss[half * HALF_STEPS + tid][row] = sum * s2k[tid];
    }
}

// Kernel 2: per-row sequential argmin scan (matches lax.scan semantics).
__global__ __launch_bounds__(256)
void mse_argmin_kernel(float* __restrict__ out) {
    int row = blockIdx.x * 256 + threadIdx.x;
    if (row >= N_ROWS) return;
    float rmin = g_aux[0][row];
    float rmax = g_aux[1][row];
    float R = fmaxf(fabsf(rmin), rmax);
    float step_sz = __fdiv_rn(R, 100.0f);      // identical expr to kernel1
    float best = 1.0e9f;
    float bmin = rmin, bmax = rmax;
    for (int j = 0; j < N_STEPS; j++) {
        float L = g_loss[j][row];               // coalesced, L2-hot
        float thres = step_sz * (float)(j + 1);
        if (L < best) { best = L; bmin = -thres; bmax = thres; }
    }
    out[row] = bmin;
    out[N_ROWS + row] = bmax;
}

extern "C" void kernel_launch(void* const* d_in, const int* in_sizes, int n_in,
                              void* d_out, int out_size) {
    const float* x = (const float*)d_in[0];
    float* out = (float*)d_out;
    dim3 grid1(N_ROWS, 2);
    mse_losses_kernel<<<grid1, THREADS>>>(x, 0x4B4000004B400000ULL);
    mse_argmin_kernel<<<N_ROWS / 256, 256>>>(out);
}